// round 6
// baseline (speedup 1.0000x reference)
#include <cuda_runtime.h>
#include <cuda_fp16.h>
#include <stdint.h>

#define NN 50000
#define NE 1600000
#define D  64
#define NCH 196          // ceil(NN/256)
#define TPB 256

// ---------------- scratch (static device globals; no allocation) ----------------
__device__ __align__(16) float  g_x0[NN * D];
__device__ __align__(16) float  g_x1[NN * D];
__device__ __align__(16) __half g_h0[NN * D];
__device__ __align__(16) __half g_h1[NN * D];
__device__ __align__(16) float  g_acc[NN * D];
__device__ float g_invdeg[NN];
__device__ int   g_deg[NN];
__device__ int   g_fill[NN];
__device__ int   g_rowstart[NN + 1];
__device__ int   g_src[NE];
__device__ int   g_dst[NE];
__device__ int   g_csr[NE];
__device__ int   g_is64;
__device__ int   g_chunksum[256];
__device__ int   g_chunkbase[256];

// ---------------- grid barrier state ----------------
__device__ unsigned g_barcnt = 0;
__device__ volatile unsigned g_bargen = 0;

__device__ __forceinline__ void grid_barrier() {
    __syncthreads();
    __threadfence();                       // release: push writes to L2 (+ L1 inval)
    if (threadIdx.x == 0) {
        unsigned gen = g_bargen;
        if (atomicAdd(&g_barcnt, 1u) == gridDim.x - 1u) {
            g_barcnt = 0;
            __threadfence();
            g_bargen = gen + 1u;
        } else {
            while (g_bargen == gen) __nanosleep(64);
        }
    }
    __syncthreads();
    __threadfence();                       // acquire: invalidate L1 before reads
}

// ---------------- packed f32x2 helpers ----------------
__device__ __forceinline__ unsigned long long dup2(float a) {
    unsigned long long r;
    asm("mov.b64 %0, {%1, %1};" : "=l"(r) : "f"(a));
    return r;
}
__device__ __forceinline__ void fma2(unsigned long long& d, unsigned long long a,
                                     unsigned long long b) {
    asm("fma.rn.f32x2 %0, %1, %2, %0;" : "+l"(d) : "l"(a), "l"(b));
}
__device__ __forceinline__ float2 ull2f2(unsigned long long v) {
    float2 f;
    asm("mov.b64 {%0, %1}, %2;" : "=f"(f.x), "=f"(f.y) : "l"(v));
    return f;
}
__device__ __forceinline__ uint2 pack_half4(float a, float b, float c, float d) {
    __half2 lo = __floats2half2_rn(a, b);
    __half2 hi = __floats2half2_rn(c, d);
    uint2 r;
    r.x = *reinterpret_cast<uint32_t*>(&lo);
    r.y = *reinterpret_cast<uint32_t*>(&hi);
    return r;
}

// ---------------- phase: input projection tile (BM=128, BN=32, BK=32) ----------------
template <int DIN>
__device__ void proj_tile(char* sraw, const float* __restrict__ X,
                          const float* __restrict__ W, const float* __restrict__ b,
                          int colOff, int tileIdx) {
    float (*sA)[33] = reinterpret_cast<float(*)[33]>(sraw);              // 128x33
    float (*sW)[32] = reinterpret_cast<float(*)[32]>(sraw + 128 * 33 * 4);
    const int t  = threadIdx.x;
    const int i0 = tileIdx * 128;
    const int tx = t & 7;
    const int ty = t >> 3;
    const int c4 = t & 7;
    const int rl = t >> 3;

    unsigned long long racc2[4][2];
#pragma unroll
    for (int r = 0; r < 4; r++) { racc2[r][0] = 0ULL; racc2[r][1] = 0ULL; }

    for (int k0 = 0; k0 < DIN; k0 += 32) {
#pragma unroll
        for (int p = 0; p < 4; p++) {
            int row = rl + p * 32;
            int gi  = i0 + row;
            float4 v = make_float4(0.f, 0.f, 0.f, 0.f);
            if (gi < NN)
                v = *reinterpret_cast<const float4*>(&X[(size_t)gi * DIN + k0 + c4 * 4]);
            sA[row][c4 * 4 + 0] = v.x;
            sA[row][c4 * 4 + 1] = v.y;
            sA[row][c4 * 4 + 2] = v.z;
            sA[row][c4 * 4 + 3] = v.w;
        }
        {
            float4 w = *reinterpret_cast<const float4*>(&W[(size_t)(k0 + rl) * 32 + c4 * 4]);
            sW[rl][c4 * 4 + 0] = w.x;
            sW[rl][c4 * 4 + 1] = w.y;
            sW[rl][c4 * 4 + 2] = w.z;
            sW[rl][c4 * 4 + 3] = w.w;
        }
        __syncthreads();
#pragma unroll
        for (int kk = 0; kk < 32; kk++) {
            ulonglong2 wp = *reinterpret_cast<const ulonglong2*>(&sW[kk][tx * 4]);
            unsigned long long a0 = dup2(sA[ty * 4 + 0][kk]);
            unsigned long long a1 = dup2(sA[ty * 4 + 1][kk]);
            unsigned long long a2 = dup2(sA[ty * 4 + 2][kk]);
            unsigned long long a3 = dup2(sA[ty * 4 + 3][kk]);
            fma2(racc2[0][0], a0, wp.x); fma2(racc2[0][1], a0, wp.y);
            fma2(racc2[1][0], a1, wp.x); fma2(racc2[1][1], a1, wp.y);
            fma2(racc2[2][0], a2, wp.x); fma2(racc2[2][1], a2, wp.y);
            fma2(racc2[3][0], a3, wp.x); fma2(racc2[3][1], a3, wp.y);
        }
        __syncthreads();
    }

    float b0 = b[tx * 4 + 0], b1 = b[tx * 4 + 1], b2 = b[tx * 4 + 2], b3 = b[tx * 4 + 3];
#pragma unroll
    for (int r = 0; r < 4; r++) {
        int gi = i0 + ty * 4 + r;
        if (gi < NN) {
            float2 p0 = ull2f2(racc2[r][0]);
            float2 p1 = ull2f2(racc2[r][1]);
            float4 v;
            v.x = p0.x + b0;
            v.y = p0.y + b1;
            v.z = p1.x + b2;
            v.w = p1.y + b3;
            *reinterpret_cast<float4*>(&g_x0[(size_t)gi * D + colOff + tx * 4]) = v;
            *reinterpret_cast<uint2*>(&g_h0[(size_t)gi * D + colOff + tx * 4]) =
                pack_half4(v.x, v.y, v.z, v.w);
        }
    }
    __syncthreads();
}

// ---------------- phase: aggregation (fp16 gather, L2 loads) ----------------
__device__ void agg_phase(const __half* __restrict__ hin, int gwarp, int gnw) {
    const int lane = threadIdx.x & 31;
    const int q  = lane >> 3;
    const int l8 = lane & 7;
    const uint4* h8 = reinterpret_cast<const uint4*>(hin);

    for (int node = gwarp; node < NN; node += gnw) {
        int beg = g_rowstart[node];
        int end = g_rowstart[node + 1];
        float acc[8];
#pragma unroll
        for (int k = 0; k < 8; k++) acc[k] = 0.f;

        int j = beg + q;
        for (; j + 4 < end; j += 8) {
            int s0 = g_csr[j];
            int s1 = g_csr[j + 4];
            uint4 a = __ldcg(&h8[(size_t)s0 * 8 + l8]);
            uint4 b = __ldcg(&h8[(size_t)s1 * 8 + l8]);
#pragma unroll
            for (int w = 0; w < 4; w++) {
                uint32_t ua = (&a.x)[w];
                uint32_t ub = (&b.x)[w];
                float2 fa = __half22float2(*reinterpret_cast<__half2*>(&ua));
                float2 fb = __half22float2(*reinterpret_cast<__half2*>(&ub));
                acc[w * 2 + 0] += fa.x + fb.x;
                acc[w * 2 + 1] += fa.y + fb.y;
            }
        }
        if (j < end) {
            int s0 = g_csr[j];
            uint4 a = __ldcg(&h8[(size_t)s0 * 8 + l8]);
#pragma unroll
            for (int w = 0; w < 4; w++) {
                uint32_t ua = (&a.x)[w];
                float2 fa = __half22float2(*reinterpret_cast<__half2*>(&ua));
                acc[w * 2 + 0] += fa.x;
                acc[w * 2 + 1] += fa.y;
            }
        }
#pragma unroll
        for (int k = 0; k < 8; k++) {
            acc[k] += __shfl_xor_sync(0xFFFFFFFFu, acc[k], 8);
            acc[k] += __shfl_xor_sync(0xFFFFFFFFu, acc[k], 16);
        }
        if (q == 0) {
            float id = g_invdeg[node];
            float4 v0 = make_float4(acc[0] * id, acc[1] * id, acc[2] * id, acc[3] * id);
            float4 v1 = make_float4(acc[4] * id, acc[5] * id, acc[6] * id, acc[7] * id);
            float4* dst = reinterpret_cast<float4*>(&g_acc[(size_t)node * D + l8 * 8]);
            dst[0] = v0;
            dst[1] = v1;
        }
    }
}

// ---------------- phase: SAGE layer GEMM tile (BM=64, BN=64, K=128) ----------------
__device__ void layer_tile(char* sraw, const float* __restrict__ xin,
                           const float* __restrict__ Wl, const float* __restrict__ bl,
                           const float* __restrict__ Wr, float* __restrict__ xout,
                           __half* __restrict__ hout, int tileIdx) {
    float (*sA)[65]  = reinterpret_cast<float(*)[65]>(sraw);             // 64x65
    float (*sW)[64]  = reinterpret_cast<float(*)[64]>(sraw + 64 * 65 * 4);
    const int t  = threadIdx.x;
    const int i0 = tileIdx * 64;
    const int tx = t & 15;
    const int ty = t >> 4;
    const int c4 = t & 15;
    const int r0 = t >> 4;

    unsigned long long racc2[4][2];
#pragma unroll
    for (int r = 0; r < 4; r++) { racc2[r][0] = 0ULL; racc2[r][1] = 0ULL; }

    for (int half = 0; half < 2; half++) {
        const float* srcmat = (half == 0) ? g_acc : xin;
        const float* Wm     = (half == 0) ? Wl : Wr;
#pragma unroll
        for (int p = 0; p < 4; p++) {
            int row = r0 + p * 16;
            int gi  = i0 + row;
            float4 v = make_float4(0.f, 0.f, 0.f, 0.f);
            if (gi < NN)
                v = __ldcg(reinterpret_cast<const float4*>(&srcmat[(size_t)gi * D + c4 * 4]));
            sA[row][c4 * 4 + 0] = v.x;
            sA[row][c4 * 4 + 1] = v.y;
            sA[row][c4 * 4 + 2] = v.z;
            sA[row][c4 * 4 + 3] = v.w;
        }
#pragma unroll
        for (int p = 0; p < 4; p++) {
            int row = r0 + p * 16;
            float4 w = *reinterpret_cast<const float4*>(&Wm[(size_t)row * 64 + c4 * 4]);
            sW[row][c4 * 4 + 0] = w.x;
            sW[row][c4 * 4 + 1] = w.y;
            sW[row][c4 * 4 + 2] = w.z;
            sW[row][c4 * 4 + 3] = w.w;
        }
        __syncthreads();
#pragma unroll
        for (int kk = 0; kk < 64; kk++) {
            ulonglong2 wp = *reinterpret_cast<const ulonglong2*>(&sW[kk][tx * 4]);
            unsigned long long a0 = dup2(sA[ty * 4 + 0][kk]);
            unsigned long long a1 = dup2(sA[ty * 4 + 1][kk]);
            unsigned long long a2 = dup2(sA[ty * 4 + 2][kk]);
            unsigned long long a3 = dup2(sA[ty * 4 + 3][kk]);
            fma2(racc2[0][0], a0, wp.x); fma2(racc2[0][1], a0, wp.y);
            fma2(racc2[1][0], a1, wp.x); fma2(racc2[1][1], a1, wp.y);
            fma2(racc2[2][0], a2, wp.x); fma2(racc2[2][1], a2, wp.y);
            fma2(racc2[3][0], a3, wp.x); fma2(racc2[3][1], a3, wp.y);
        }
        __syncthreads();
    }

    float b0 = bl[tx * 4 + 0], b1 = bl[tx * 4 + 1], b2 = bl[tx * 4 + 2], b3 = bl[tx * 4 + 3];
#pragma unroll
    for (int r = 0; r < 4; r++) {
        int gi = i0 + ty * 4 + r;
        if (gi < NN) {
            float2 p0 = ull2f2(racc2[r][0]);
            float2 p1 = ull2f2(racc2[r][1]);
            float4 v;
            v.x = fmaxf(p0.x + b0, 0.f);
            v.y = fmaxf(p0.y + b1, 0.f);
            v.z = fmaxf(p1.x + b2, 0.f);
            v.w = fmaxf(p1.y + b3, 0.f);
            *reinterpret_cast<float4*>(&xout[(size_t)gi * D + tx * 4]) = v;
            if (hout)
                *reinterpret_cast<uint2*>(&hout[(size_t)gi * D + tx * 4]) =
                    pack_half4(v.x, v.y, v.z, v.w);
        }
    }
    __syncthreads();
}

// ---------------- the single persistent kernel ----------------
__global__ void __launch_bounds__(TPB)
fused_kernel(const float* __restrict__ x_content, const float* __restrict__ x_style,
             const void* __restrict__ edge_idx,
             const float* __restrict__ Wp, const float* __restrict__ bp,
             const float* __restrict__ Ws, const float* __restrict__ bs,
             const float* __restrict__ Wl1, const float* __restrict__ bl1,
             const float* __restrict__ Wr1,
             const float* __restrict__ Wl2, const float* __restrict__ bl2,
             const float* __restrict__ Wr2,
             const float* __restrict__ Wl3, const float* __restrict__ bl3,
             const float* __restrict__ Wr3,
             const float* __restrict__ Wo, const float* __restrict__ bo,
             float* __restrict__ out) {
    __shared__ __align__(16) char sraw[64 * 65 * 4 + 64 * 64 * 4];  // 33 KB, reused per phase

    const int t       = threadIdx.x;
    const int gtid    = blockIdx.x * TPB + t;
    const int gstride = gridDim.x * TPB;
    const int gwarp   = gtid >> 5;
    const int gnw     = gstride >> 5;
    const int lane    = t & 31;
    int* shi = reinterpret_cast<int*>(sraw);

    // ---- P0: zero counters + dtype detect ----
    for (int i = gtid; i < NN; i += gstride) { g_deg[i] = 0; g_fill[i] = 0; }
    if (blockIdx.x == 0) {
        long long v = reinterpret_cast<const long long*>(edge_idx)[t];
        int ok = (v >= 0 && v < NN) ? 1 : 0;
        int all = __syncthreads_and(ok);
        if (t == 0) g_is64 = all;
    }
    grid_barrier();

    // ---- P1: edge prep + degree histogram ----
    {
        const int is64 = g_is64;
        if (is64) {
            const long long* p = reinterpret_cast<const long long*>(edge_idx);
            for (int e = gtid; e < NE; e += gstride) {
                int s = (int)p[e];
                int d = (int)p[NE + e];
                g_src[e] = s;
                g_dst[e] = d;
                atomicAdd(&g_deg[d], 1);
            }
        } else {
            const int* p = reinterpret_cast<const int*>(edge_idx);
            for (int e = gtid; e < NE; e += gstride) {
                int s = p[e];
                int d = p[NE + e];
                g_src[e] = s;
                g_dst[e] = d;
                atomicAdd(&g_deg[d], 1);
            }
        }
    }
    grid_barrier();

    // ---- P2a: chunk sums (256 nodes per chunk) ----
    for (int c = blockIdx.x; c < NCH; c += gridDim.x) {
        int i = c * 256 + t;
        int v = (i < NN) ? g_deg[i] : 0;
        shi[t] = v;
        __syncthreads();
#pragma unroll
        for (int off = 128; off > 0; off >>= 1) {
            if (t < off) shi[t] += shi[t + off];
            __syncthreads();
        }
        if (t == 0) g_chunksum[c] = shi[0];
        __syncthreads();
    }
    grid_barrier();

    // ---- P2b: scan of chunk sums (block 0) ----
    if (blockIdx.x == 0) {
        int v = (t < NCH) ? g_chunksum[t] : 0;
        shi[t] = v;
        __syncthreads();
#pragma unroll
        for (int off = 1; off < 256; off <<= 1) {
            int u = (t >= off) ? shi[t - off] : 0;
            __syncthreads();
            shi[t] += u;
            __syncthreads();
        }
        if (t < NCH) g_chunkbase[t] = shi[t] - v;
        if (t == 255) g_rowstart[NN] = shi[t];
    }
    grid_barrier();

    // ---- P2c: in-chunk exclusive scan + invdeg ----
    for (int c = blockIdx.x; c < NCH; c += gridDim.x) {
        int i = c * 256 + t;
        int v = (i < NN) ? g_deg[i] : 0;
        shi[t] = v;
        __syncthreads();
#pragma unroll
        for (int off = 1; off < 256; off <<= 1) {
            int u = (t >= off) ? shi[t - off] : 0;
            __syncthreads();
            shi[t] += u;
            __syncthreads();
        }
        if (i < NN) {
            g_rowstart[i] = g_chunkbase[c] + shi[t] - v;
            g_invdeg[i]   = 1.0f / fmaxf((float)v, 1.0f);
        }
        __syncthreads();
    }
    grid_barrier();

    // ---- P3: CSR fill ----
    for (int e = gtid; e < NE; e += gstride) {
        int d = g_dst[e];
        int slot = g_rowstart[d] + atomicAdd(&g_fill[d], 1);
        g_csr[slot] = g_src[e];
    }
    grid_barrier();

    // ---- P4: input projections -> x0/h0 ----
    {
        const int T768 = (NN + 127) / 128;           // 391
        const int TALL = 2 * T768;                   // content tiles then style tiles
        for (int tile = blockIdx.x; tile < TALL; tile += gridDim.x) {
            if (tile < T768) proj_tile<768>(sraw, x_content, Wp, bp, 0, tile);
            else             proj_tile<128>(sraw, x_style,  Ws, bs, 32, tile - T768);
        }
    }
    grid_barrier();

    const int LT = (NN + 63) / 64;                   // 782 layer tiles

    // ---- layer 1 ----
    agg_phase(g_h0, gwarp, gnw);
    grid_barrier();
    for (int tile = blockIdx.x; tile < LT; tile += gridDim.x)
        layer_tile(sraw, g_x0, Wl1, bl1, Wr1, g_x1, g_h1, tile);
    grid_barrier();

    // ---- layer 2 ----
    agg_phase(g_h1, gwarp, gnw);
    grid_barrier();
    for (int tile = blockIdx.x; tile < LT; tile += gridDim.x)
        layer_tile(sraw, g_x1, Wl2, bl2, Wr2, g_x0, g_h0, tile);
    grid_barrier();

    // ---- layer 3 ----
    agg_phase(g_h0, gwarp, gnw);
    grid_barrier();
    for (int tile = blockIdx.x; tile < LT; tile += gridDim.x)
        layer_tile(sraw, g_x0, Wl3, bl3, Wr3, g_x1, (__half*)nullptr, tile);
    grid_barrier();

    // ---- head: out = x1 @ Wo + bo ----
    {
        float w0a = Wo[lane * 2 + 0], w1a = Wo[lane * 2 + 1];
        float w0b = Wo[(lane + 32) * 2 + 0], w1b = Wo[(lane + 32) * 2 + 1];
        float bo0 = bo[0], bo1 = bo[1];
        for (int node = gwarp; node < NN; node += gnw) {
            float2 xv = __ldcg(reinterpret_cast<const float2*>(&g_x1[(size_t)node * D]) + lane);
            float p0 = xv.x * w0a + xv.y * Wo[(2 * lane + 1) * 2 + 0];
            float p1 = xv.x * w1a + xv.y * Wo[(2 * lane + 1) * 2 + 1];
            // note: lane covers elements 2*lane and 2*lane+1
            p0 = xv.x * Wo[(2 * lane) * 2 + 0] + xv.y * Wo[(2 * lane + 1) * 2 + 0];
            p1 = xv.x * Wo[(2 * lane) * 2 + 1] + xv.y * Wo[(2 * lane + 1) * 2 + 1];
#pragma unroll
            for (int o = 16; o > 0; o >>= 1) {
                p0 += __shfl_xor_sync(0xFFFFFFFFu, p0, o);
                p1 += __shfl_xor_sync(0xFFFFFFFFu, p1, o);
            }
            if (lane == 0) {
                out[node * 2 + 0] = p0 + bo0;
                out[node * 2 + 1] = p1 + bo1;
            }
        }
        (void)w0b; (void)w1b;
    }
}

// ---------------- launch ----------------
extern "C" void kernel_launch(void* const* d_in, const int* in_sizes, int n_in,
                              void* d_out, int out_size) {
    const float* x_content = (const float*)d_in[0];
    const float* x_style   = (const float*)d_in[1];
    const void*  edge_idx  = d_in[2];
    // d_in[3] = edge_type (unused by the model)
    const float* Wp  = (const float*)d_in[4];
    const float* bp  = (const float*)d_in[5];
    const float* Ws  = (const float*)d_in[6];
    const float* bs  = (const float*)d_in[7];
    const float* Wl1 = (const float*)d_in[8];
    const float* bl1 = (const float*)d_in[9];
    const float* Wr1 = (const float*)d_in[10];
    const float* Wl2 = (const float*)d_in[11];
    const float* bl2 = (const float*)d_in[12];
    const float* Wr2 = (const float*)d_in[13];
    const float* Wl3 = (const float*)d_in[14];
    const float* bl3 = (const float*)d_in[15];
    const float* Wr3 = (const float*)d_in[16];
    const float* Wo  = (const float*)d_in[17];
    const float* bo  = (const float*)d_in[18];
    float* out = (float*)d_out;

    int dev = 0;
    cudaGetDevice(&dev);
    int nsm = 148;
    cudaDeviceGetAttribute(&nsm, cudaDevAttrMultiProcessorCount, dev);
    int occ = 1;
    cudaOccupancyMaxActiveBlocksPerMultiprocessor(&occ, fused_kernel, TPB, 0);
    if (occ < 1) occ = 1;
    int G = nsm * occ;

    fused_kernel<<<G, TPB>>>(x_content, x_style, edge_idx,
                             Wp, bp, Ws, bs,
                             Wl1, bl1, Wr1, Wl2, bl2, Wr2, Wl3, bl3, Wr3,
                             Wo, bo, out);
}

// round 7
// speedup vs baseline: 1.3448x; 1.3448x over previous
#include <cuda_runtime.h>
#include <cuda_fp16.h>
#include <stdint.h>

#define NN 50000
#define NE 1600000
#define D  64
#define NBLK 49   // ceil(NN/1024)

// ---------------- scratch (static device globals; no allocation) ----------------
__device__ __align__(16) float  g_x0[NN * D];
__device__ __align__(16) float  g_x1[NN * D];
__device__ __align__(16) __half g_h0[NN * D];
__device__ __align__(16) __half g_h1[NN * D];
__device__ __align__(16) float  g_acc[NN * D];
__device__ float g_invdeg[NN];
__device__ int   g_deg[NN];
__device__ int   g_fill[NN];
__device__ int   g_rowstart[NN + 1];
__device__ int   g_src[NE];
__device__ int   g_dst[NE];
__device__ int   g_csr[NE];
__device__ int   g_is64;
__device__ int   g_blocksum[NBLK];
__device__ int   g_blockbase[NBLK];

// ---------------- tf32 helpers ----------------
__device__ __forceinline__ uint32_t f2tf32(float x) {
    uint32_t r;
    asm("cvt.rna.tf32.f32 %0, %1;" : "=r"(r) : "f"(x));
    return r;
}
__device__ __forceinline__ void mma_tf32(float c[4], uint32_t a0, uint32_t a1,
                                         uint32_t a2, uint32_t a3,
                                         uint32_t b0, uint32_t b1) {
    asm volatile(
        "mma.sync.aligned.m16n8k8.row.col.f32.tf32.tf32.f32 "
        "{%0,%1,%2,%3}, {%4,%5,%6,%7}, {%8,%9}, {%0,%1,%2,%3};"
        : "+f"(c[0]), "+f"(c[1]), "+f"(c[2]), "+f"(c[3])
        : "r"(a0), "r"(a1), "r"(a2), "r"(a3), "r"(b0), "r"(b1));
}
__device__ __forceinline__ uint4 tf32x4(float4 v) {
    uint4 u;
    u.x = f2tf32(v.x); u.y = f2tf32(v.y); u.z = f2tf32(v.z); u.w = f2tf32(v.w);
    return u;
}

// ---------------- dtype probe ----------------
__global__ void detect_kernel(const long long* __restrict__ p) {
    int t = threadIdx.x;
    long long v = p[t];
    int ok = (v >= 0 && v < NN) ? 1 : 0;
    int all = __syncthreads_and(ok);
    if (t == 0) g_is64 = all;
}

__global__ void zero_cnt_kernel() {
    int i = blockIdx.x * blockDim.x + threadIdx.x;
    if (i < NN) { g_deg[i] = 0; g_fill[i] = 0; }
}

__global__ void prep_edges_kernel(const void* __restrict__ ei) {
    int e = blockIdx.x * blockDim.x + threadIdx.x;
    if (e >= NE) return;
    int s, d;
    if (g_is64) {
        const long long* p = (const long long*)ei;
        s = (int)p[e];
        d = (int)p[NE + e];
    } else {
        const int* p = (const int*)ei;
        s = p[e];
        d = p[NE + e];
    }
    g_src[e] = s;
    g_dst[e] = d;
    atomicAdd(&g_deg[d], 1);
}

// ---------------- scan (3 phases) ----------------
__global__ void scan1_kernel() {
    __shared__ int sh[1024];
    int t = threadIdx.x;
    int i = blockIdx.x * 1024 + t;
    int v = (i < NN) ? g_deg[i] : 0;
    sh[t] = v;
    __syncthreads();
#pragma unroll
    for (int off = 512; off > 0; off >>= 1) {
        if (t < off) sh[t] += sh[t + off];
        __syncthreads();
    }
    if (t == 0) g_blocksum[blockIdx.x] = sh[0];
}

__global__ void scan2_kernel() {
    __shared__ int sh[64];
    int t = threadIdx.x;
    int v = (t < NBLK) ? g_blocksum[t] : 0;
    sh[t] = v;
    __syncthreads();
#pragma unroll
    for (int off = 1; off < 64; off <<= 1) {
        int u = (t >= off) ? sh[t - off] : 0;
        __syncthreads();
        sh[t] += u;
        __syncthreads();
    }
    if (t < NBLK) g_blockbase[t] = sh[t] - v;
    if (t == NBLK - 1) g_rowstart[NN] = sh[t];
}

__global__ void scan3_kernel() {
    __shared__ int sh[1024];
    int t = threadIdx.x;
    int i = blockIdx.x * 1024 + t;
    int v = (i < NN) ? g_deg[i] : 0;
    sh[t] = v;
    __syncthreads();
#pragma unroll
    for (int off = 1; off < 1024; off <<= 1) {
        int u = (t >= off) ? sh[t - off] : 0;
        __syncthreads();
        sh[t] += u;
        __syncthreads();
    }
    if (i < NN) {
        g_rowstart[i] = g_blockbase[blockIdx.x] + sh[t] - v;
        g_invdeg[i] = 1.0f / fmaxf((float)v, 1.0f);
    }
}

__global__ void csr_fill_kernel() {
    int e = blockIdx.x * blockDim.x + threadIdx.x;
    if (e >= NE) return;
    int d = g_dst[e];
    int slot = g_rowstart[d] + atomicAdd(&g_fill[d], 1);
    g_csr[slot] = g_src[e];
}

__device__ __forceinline__ uint2 pack_half4(float a, float b, float c, float d) {
    __half2 lo = __floats2half2_rn(a, b);
    __half2 hi = __floats2half2_rn(c, d);
    uint2 r;
    r.x = *reinterpret_cast<uint32_t*>(&lo);
    r.y = *reinterpret_cast<uint32_t*>(&hi);
    return r;
}

// ---------------- input projection via tf32 MMA ----------------
// out[:, colOff:colOff+32] = X @ W + b ; also fp16 shadow.
// BM=128 (8 warps x 16 rows), N=32 (4 n-tiles), K chunks of 64.
template <int DIN>
__global__ void __launch_bounds__(256)
proj_mma_kernel(const float* __restrict__ X, const float* __restrict__ W,
                const float* __restrict__ b, float* __restrict__ out,
                __half* __restrict__ hout, int colOff) {
    __shared__ uint32_t sA[128][68];   // 34.8 KB
    __shared__ uint32_t sW[64][36];    //  9.2 KB
    const int t    = threadIdx.x;
    const int warp = t >> 5;
    const int lane = t & 31;
    const int g    = lane >> 2;
    const int tig  = lane & 3;
    const int i0   = blockIdx.x * 128;
    const int mrow = warp * 16;        // warp's row base within tile

    float c[4][4];
#pragma unroll
    for (int n = 0; n < 4; n++)
#pragma unroll
        for (int k = 0; k < 4; k++) c[n][k] = 0.f;

    for (int k0 = 0; k0 < DIN; k0 += 64) {
        // fill sA: 128 rows x 64 k (2048 float4)
#pragma unroll
        for (int f = t; f < 2048; f += 256) {
            int row = f >> 4, c4 = f & 15;
            int gi  = i0 + row;
            float4 v = make_float4(0.f, 0.f, 0.f, 0.f);
            if (gi < NN)
                v = *reinterpret_cast<const float4*>(&X[(size_t)gi * DIN + k0 + c4 * 4]);
            *reinterpret_cast<uint4*>(&sA[row][c4 * 4]) = tf32x4(v);
        }
        // fill sW: 64 k x 32 n (512 float4)
#pragma unroll
        for (int f = t; f < 512; f += 256) {
            int row = f >> 3, c4 = f & 7;
            float4 v = *reinterpret_cast<const float4*>(&W[(size_t)(k0 + row) * 32 + c4 * 4]);
            *reinterpret_cast<uint4*>(&sW[row][c4 * 4]) = tf32x4(v);
        }
        __syncthreads();
#pragma unroll
        for (int ks = 0; ks < 8; ks++) {
            uint32_t a0 = sA[mrow + g][ks * 8 + tig];
            uint32_t a1 = sA[mrow + g + 8][ks * 8 + tig];
            uint32_t a2 = sA[mrow + g][ks * 8 + tig + 4];
            uint32_t a3 = sA[mrow + g + 8][ks * 8 + tig + 4];
#pragma unroll
            for (int nt = 0; nt < 4; nt++) {
                uint32_t b0 = sW[ks * 8 + tig][nt * 8 + g];
                uint32_t b1 = sW[ks * 8 + tig + 4][nt * 8 + g];
                mma_tf32(c[nt], a0, a1, a2, a3, b0, b1);
            }
        }
        __syncthreads();
    }

    // epilogue: bias, store fp32 + fp16
#pragma unroll
    for (int nt = 0; nt < 4; nt++) {
        int col = nt * 8 + 2 * tig;                  // 0..31 within proj block
        float bx = b[col], by = b[col + 1];
        int row0 = i0 + mrow + g;
        int row1 = row0 + 8;
        int ocol = colOff + col;
        if (row0 < NN) {
            float2 v = make_float2(c[nt][0] + bx, c[nt][1] + by);
            *reinterpret_cast<float2*>(&out[(size_t)row0 * D + ocol]) = v;
            __half2 h = __floats2half2_rn(v.x, v.y);
            *reinterpret_cast<__half2*>(&hout[(size_t)row0 * D + ocol]) = h;
        }
        if (row1 < NN) {
            float2 v = make_float2(c[nt][2] + bx, c[nt][3] + by);
            *reinterpret_cast<float2*>(&out[(size_t)row1 * D + ocol]) = v;
            __half2 h = __floats2half2_rn(v.x, v.y);
            *reinterpret_cast<__half2*>(&hout[(size_t)row1 * D + ocol]) = h;
        }
    }
}

// ---------------- gather aggregation (fp16 rows) ----------------
__global__ void aggregate_kernel(const __half* __restrict__ hin) {
    int warp = (blockIdx.x * blockDim.x + threadIdx.x) >> 5;
    int lane = threadIdx.x & 31;
    if (warp >= NN) return;
    const int q  = lane >> 3;
    const int l8 = lane & 7;
    int beg = g_rowstart[warp];
    int end = g_rowstart[warp + 1];
    const uint4* h8 = reinterpret_cast<const uint4*>(hin);

    float acc[8];
#pragma unroll
    for (int k = 0; k < 8; k++) acc[k] = 0.f;

    int j = beg + q;
    for (; j + 4 < end; j += 8) {
        int s0 = g_csr[j];
        int s1 = g_csr[j + 4];
        uint4 a = __ldg(&h8[(size_t)s0 * 8 + l8]);
        uint4 b = __ldg(&h8[(size_t)s1 * 8 + l8]);
#pragma unroll
        for (int w = 0; w < 4; w++) {
            uint32_t ua = (&a.x)[w];
            uint32_t ub = (&b.x)[w];
            float2 fa = __half22float2(*reinterpret_cast<__half2*>(&ua));
            float2 fb = __half22float2(*reinterpret_cast<__half2*>(&ub));
            acc[w * 2 + 0] += fa.x + fb.x;
            acc[w * 2 + 1] += fa.y + fb.y;
        }
    }
    if (j < end) {
        int s0 = g_csr[j];
        uint4 a = __ldg(&h8[(size_t)s0 * 8 + l8]);
#pragma unroll
        for (int w = 0; w < 4; w++) {
            uint32_t ua = (&a.x)[w];
            float2 fa = __half22float2(*reinterpret_cast<__half2*>(&ua));
            acc[w * 2 + 0] += fa.x;
            acc[w * 2 + 1] += fa.y;
        }
    }
#pragma unroll
    for (int k = 0; k < 8; k++) {
        acc[k] += __shfl_xor_sync(0xFFFFFFFFu, acc[k], 8);
        acc[k] += __shfl_xor_sync(0xFFFFFFFFu, acc[k], 16);
    }
    if (q == 0) {
        float id = g_invdeg[warp];
        float4 v0 = make_float4(acc[0] * id, acc[1] * id, acc[2] * id, acc[3] * id);
        float4 v1 = make_float4(acc[4] * id, acc[5] * id, acc[6] * id, acc[7] * id);
        float4* dst = reinterpret_cast<float4*>(&g_acc[(size_t)warp * D + l8 * 8]);
        dst[0] = v0;
        dst[1] = v1;
    }
}

// ---------------- SAGE layer via tf32 MMA ----------------
// xout = relu(acc @ Wl + xin @ Wr + bl); optional fp16 shadow.
// BM=64: 4 m-tiles x 2 n-halves = 8 warps. K=64 per half, 8 k-steps.
__global__ void __launch_bounds__(256)
layer_mma_kernel(const float* __restrict__ xin, const float* __restrict__ Wl,
                 const float* __restrict__ bl, const float* __restrict__ Wr,
                 float* __restrict__ xout, __half* __restrict__ hout) {
    __shared__ uint32_t sA[64][68];
    __shared__ uint32_t sW[64][68];
    const int t    = threadIdx.x;
    const int warp = t >> 5;
    const int lane = t & 31;
    const int g    = lane >> 2;
    const int tig  = lane & 3;
    const int i0   = blockIdx.x * 64;
    const int mrow = (warp >> 1) * 16;   // m-tile base (0,16,32,48)
    const int nh   = (warp & 1) * 32;    // n half (0 or 32)

    float c[4][4];
#pragma unroll
    for (int n = 0; n < 4; n++)
#pragma unroll
        for (int k = 0; k < 4; k++) c[n][k] = 0.f;

#pragma unroll
    for (int half = 0; half < 2; half++) {
        const float* src = (half == 0) ? g_acc : xin;
        const float* Wm  = (half == 0) ? Wl : Wr;
        // fill sA: 64 rows x 64 k (1024 float4)
#pragma unroll
        for (int f = t; f < 1024; f += 256) {
            int row = f >> 4, c4 = f & 15;
            int gi  = i0 + row;
            float4 v = make_float4(0.f, 0.f, 0.f, 0.f);
            if (gi < NN)
                v = *reinterpret_cast<const float4*>(&src[(size_t)gi * D + c4 * 4]);
            *reinterpret_cast<uint4*>(&sA[row][c4 * 4]) = tf32x4(v);
        }
        // fill sW: 64 k x 64 n (1024 float4)
#pragma unroll
        for (int f = t; f < 1024; f += 256) {
            int row = f >> 4, c4 = f & 15;
            float4 v = *reinterpret_cast<const float4*>(&Wm[(size_t)row * 64 + c4 * 4]);
            *reinterpret_cast<uint4*>(&sW[row][c4 * 4]) = tf32x4(v);
        }
        __syncthreads();
#pragma unroll
        for (int ks = 0; ks < 8; ks++) {
            uint32_t a0 = sA[mrow + g][ks * 8 + tig];
            uint32_t a1 = sA[mrow + g + 8][ks * 8 + tig];
            uint32_t a2 = sA[mrow + g][ks * 8 + tig + 4];
            uint32_t a3 = sA[mrow + g + 8][ks * 8 + tig + 4];
#pragma unroll
            for (int nt = 0; nt < 4; nt++) {
                uint32_t b0 = sW[ks * 8 + tig][nh + nt * 8 + g];
                uint32_t b1 = sW[ks * 8 + tig + 4][nh + nt * 8 + g];
                mma_tf32(c[nt], a0, a1, a2, a3, b0, b1);
            }
        }
        __syncthreads();
    }

    // epilogue: bias + relu, fp32 + optional fp16
#pragma unroll
    for (int nt = 0; nt < 4; nt++) {
        int col = nh + nt * 8 + 2 * tig;
        float bx = bl[col], by = bl[col + 1];
        int row0 = i0 + mrow + g;
        int row1 = row0 + 8;
        if (row0 < NN) {
            float2 v = make_float2(fmaxf(c[nt][0] + bx, 0.f), fmaxf(c[nt][1] + by, 0.f));
            *reinterpret_cast<float2*>(&xout[(size_t)row0 * D + col]) = v;
            if (hout) {
                __half2 h = __floats2half2_rn(v.x, v.y);
                *reinterpret_cast<__half2*>(&hout[(size_t)row0 * D + col]) = h;
            }
        }
        if (row1 < NN) {
            float2 v = make_float2(fmaxf(c[nt][2] + bx, 0.f), fmaxf(c[nt][3] + by, 0.f));
            *reinterpret_cast<float2*>(&xout[(size_t)row1 * D + col]) = v;
            if (hout) {
                __half2 h = __floats2half2_rn(v.x, v.y);
                *reinterpret_cast<__half2*>(&hout[(size_t)row1 * D + col]) = h;
            }
        }
    }
}

// ---------------- output head: out = x @ Wo + bo ----------------
__global__ void head_kernel(const float* __restrict__ x, const float* __restrict__ Wo,
                            const float* __restrict__ bo, float* __restrict__ out) {
    int gw   = (blockIdx.x * blockDim.x + threadIdx.x) >> 5;
    int lane = threadIdx.x & 31;
    if (gw >= NN) return;
    float xa = x[(size_t)gw * D + lane];
    float xb = x[(size_t)gw * D + 32 + lane];
    float p0 = xa * Wo[lane * 2 + 0] + xb * Wo[(lane + 32) * 2 + 0];
    float p1 = xa * Wo[lane * 2 + 1] + xb * Wo[(lane + 32) * 2 + 1];
#pragma unroll
    for (int o = 16; o > 0; o >>= 1) {
        p0 += __shfl_xor_sync(0xFFFFFFFFu, p0, o);
        p1 += __shfl_xor_sync(0xFFFFFFFFu, p1, o);
    }
    if (lane == 0) {
        out[gw * 2 + 0] = p0 + bo[0];
        out[gw * 2 + 1] = p1 + bo[1];
    }
}

// ---------------- launch ----------------
extern "C" void kernel_launch(void* const* d_in, const int* in_sizes, int n_in,
                              void* d_out, int out_size) {
    const float* x_content = (const float*)d_in[0];
    const float* x_style   = (const float*)d_in[1];
    const void*  edge_idx  = d_in[2];
    // d_in[3] = edge_type (unused)
    const float* Wp  = (const float*)d_in[4];
    const float* bp  = (const float*)d_in[5];
    const float* Ws  = (const float*)d_in[6];
    const float* bs  = (const float*)d_in[7];
    const float* Wl1 = (const float*)d_in[8];
    const float* bl1 = (const float*)d_in[9];
    const float* Wr1 = (const float*)d_in[10];
    const float* Wl2 = (const float*)d_in[11];
    const float* bl2 = (const float*)d_in[12];
    const float* Wr2 = (const float*)d_in[13];
    const float* Wl3 = (const float*)d_in[14];
    const float* bl3 = (const float*)d_in[15];
    const float* Wr3 = (const float*)d_in[16];
    const float* Wo  = (const float*)d_in[17];
    const float* bo  = (const float*)d_in[18];
    float* out = (float*)d_out;

    float *x0, *x1;
    __half *h0, *h1;
    cudaGetSymbolAddress((void**)&x0, g_x0);
    cudaGetSymbolAddress((void**)&x1, g_x1);
    cudaGetSymbolAddress((void**)&h0, g_h0);
    cudaGetSymbolAddress((void**)&h1, g_h1);

    const int TPB = 256;

    // graph prep
    detect_kernel<<<1, 256>>>((const long long*)edge_idx);
    zero_cnt_kernel<<<(NN + TPB - 1) / TPB, TPB>>>();
    prep_edges_kernel<<<(NE + TPB - 1) / TPB, TPB>>>(edge_idx);
    scan1_kernel<<<NBLK, 1024>>>();
    scan2_kernel<<<1, 64>>>();
    scan3_kernel<<<NBLK, 1024>>>();
    csr_fill_kernel<<<(NE + TPB - 1) / TPB, TPB>>>();

    // input projection -> x0 / h0
    int projBlocks = (NN + 127) / 128;
    proj_mma_kernel<768><<<projBlocks, TPB>>>(x_content, Wp, bp, x0, h0, 0);
    proj_mma_kernel<128><<<projBlocks, TPB>>>(x_style, Ws, bs, x0, h0, 32);

    const int aggBlocks  = (NN * 32 + TPB - 1) / TPB;
    const int gemmBlocks = (NN + 63) / 64;

    // layer 1
    aggregate_kernel<<<aggBlocks, TPB>>>(h0);
    layer_mma_kernel<<<gemmBlocks, TPB>>>(x0, Wl1, bl1, Wr1, x1, h1);

    // layer 2
    aggregate_kernel<<<aggBlocks, TPB>>>(h1);
    layer_mma_kernel<<<gemmBlocks, TPB>>>(x1, Wl2, bl2, Wr2, x0, h0);

    // layer 3
    aggregate_kernel<<<aggBlocks, TPB>>>(h0);
    layer_mma_kernel<<<gemmBlocks, TPB>>>(x0, Wl3, bl3, Wr3, x1, (__half*)nullptr);

    // head
    head_kernel<<<(NN * 32 + TPB - 1) / TPB, TPB>>>(x1, Wo, bo, out);
}